// round 14
// baseline (speedup 1.0000x reference)
#include <cuda_runtime.h>
#include <float.h>
#include <math.h>

#define BB 8
#define MAXN 1024
#define MAXC 512
#define EPSV 1e-10f
#define MUSL 8

typedef unsigned long long ull;

// ------------------------- scratch (static device globals) -----------------
__device__ __align__(128) float g_X[BB * MAXN * MAXC];   // gathered target (b, i, c)
__device__ __align__(128) float g_Y[BB * MAXN * MAXC];   // gathered gen
__device__ float g_xn[BB * MAXN];
__device__ float g_yn[BB * MAXN];
__device__ float g_rowmin[4 * BB * MAXN];
__device__ float g_colmin[4 * BB * MAXN];
__device__ float g_muxp[MUSL][BB * MAXC];                // per-slice partial col sums
__device__ float g_muyp[MUSL][BB * MAXC];
__device__ float g_mux[BB * MAXC];
__device__ float g_muy[BB * MAXC];
__device__ float g_mud[4 * BB];
__device__ float g_covsum[4 * BB];
__device__ float g_m1[4 * BB];
__device__ float g_m2[4 * BB];

// ------------------------------ helpers ------------------------------------
__device__ __forceinline__ void atomicMinF(float* addr, float val) {
    if (val >= 0.f) atomicMin((int*)addr, __float_as_int(val));
    else            atomicMax((unsigned int*)addr, __float_as_uint(val));
}

__device__ __forceinline__ float blockReduceSum(float v, float* sbuf) {
    int t = threadIdx.x;
    __syncthreads();
    sbuf[t] = v;
    __syncthreads();
    for (int s = blockDim.x >> 1; s > 0; s >>= 1) {
        if (t < s) sbuf[t] += sbuf[t + s];
        __syncthreads();
    }
    return sbuf[0];
}

// packed fp32x2 FMA (Blackwell): two independent rn-FMAs per instruction
__device__ __forceinline__ ull fma2(ull a, ull b, ull c) {
    ull d;
    asm("fma.rn.f32x2 %0, %1, %2, %3;" : "=l"(d) : "l"(a), "l"(b), "l"(c));
    return d;
}
__device__ __forceinline__ ull dup2(float x) {
    ull d;
    unsigned int u = __float_as_uint(x);
    asm("mov.b64 %0, {%1, %1};" : "=l"(d) : "r"(u));
    return d;
}
__device__ __forceinline__ float2 unpk2(ull v) {
    float2 r;
    asm("mov.b64 {%0, %1}, %2;" : "=f"(r.x), "=f"(r.y) : "l"(v));
    return r;
}

// ------------------------------ init ----------------------------------------
__global__ void k_init() {
    int i = blockIdx.x * blockDim.x + threadIdx.x;
    if (i < 4 * BB * MAXN) {
        g_rowmin[i] = FLT_MAX;
        g_colmin[i] = FLT_MAX;
    }
    if (i < 4 * BB) g_covsum[i] = 0.f;
}

// ------------------------------ gather (levels 0-2) -------------------------
__global__ void k_gather(const float* __restrict__ tf, const float* __restrict__ gf,
                         const int* __restrict__ idx, int c, int hw, int N) {
    int i = blockIdx.x;
    int b = blockIdx.y;
    int p = idx[b * N + i];
    const float* ts = tf + (size_t)b * c * hw + p;
    const float* gs = gf + (size_t)b * c * hw + p;
    float* xd = g_X + ((size_t)b * N + i) * c;
    float* yd = g_Y + ((size_t)b * N + i) * c;
    for (int ch = threadIdx.x; ch < c; ch += blockDim.x) {
        xd[ch] = ts[(size_t)ch * hw];
        yd[ch] = gs[(size_t)ch * hw];
    }
}

// ------------------------------ level-3 transpose ---------------------------
__global__ void k_transpose3(const float* __restrict__ tf, const float* __restrict__ gf) {
    __shared__ float st[32][33];
    __shared__ float sg[32][33];
    int b  = blockIdx.z;
    int i0 = blockIdx.x << 5;
    int c0 = blockIdx.y << 5;
    int tx = threadIdx.x;
    int ty = threadIdx.y;
    const float* tb = tf + ((size_t)(b * 512 + c0)) * 1024 + i0;
    const float* gb = gf + ((size_t)(b * 512 + c0)) * 1024 + i0;
    for (int r = ty; r < 32; r += 8) {
        st[r][tx] = tb[(size_t)r * 1024 + tx];
        sg[r][tx] = gb[(size_t)r * 1024 + tx];
    }
    __syncthreads();
    for (int r = ty; r < 32; r += 8) {
        g_X[((size_t)b * 1024 + i0 + r) * 512 + c0 + tx] = st[tx][r];
        g_Y[((size_t)b * 1024 + i0 + r) * 512 + c0 + tx] = sg[tx][r];
    }
}

// ------------------------------ norms ---------------------------------------
__global__ void k_norms(int c) {
    __shared__ float sbuf[128];
    int r = blockIdx.x;
    const float* x = g_X + (size_t)r * c;
    const float* y = g_Y + (size_t)r * c;
    float sx = 0.f, sy = 0.f;
    for (int ch = threadIdx.x; ch < c; ch += 128) {
        float v = x[ch]; sx += v * v;
        float w = y[ch]; sy += w * w;
    }
    float tx_ = blockReduceSum(sx, sbuf);
    float ty_ = blockReduceSum(sy, sbuf);
    if (threadIdx.x == 0) {
        g_xn[r] = sqrtf(tx_);
        g_yn[r] = sqrtf(ty_);
    }
}

// ------------------------------ mu partial sums ------------------------------
// grid (c/64, MUSL, B), block (64, 4). Each slice sums its row range per channel.
__global__ void k_musum(int c, int N) {
    __shared__ float shx[4][64], shy[4][64];
    int b  = blockIdx.z;
    int sl = blockIdx.y;
    int ch = (blockIdx.x << 6) + threadIdx.x;
    int len = (N + MUSL - 1) / MUSL;
    int r0 = sl * len;
    int r1 = min(N, r0 + len);
    const float* x = g_X + (size_t)b * N * c + ch;
    const float* y = g_Y + (size_t)b * N * c + ch;
    float sx = 0.f, sy = 0.f;
    for (int i = r0 + threadIdx.y; i < r1; i += 4) {
        sx += x[(size_t)i * c];
        sy += y[(size_t)i * c];
    }
    shx[threadIdx.y][threadIdx.x] = sx;
    shy[threadIdx.y][threadIdx.x] = sy;
    __syncthreads();
    if (threadIdx.y == 0) {
        int p = threadIdx.x;
        g_muxp[sl][b * c + ch] = shx[0][p] + shx[1][p] + shx[2][p] + shx[3][p];
        g_muyp[sl][b * c + ch] = shy[0][p] + shy[1][p] + shy[2][p] + shy[3][p];
    }
}

// ------------------------------ mu finalize + mu_d ---------------------------
__global__ void k_mufin(int lvl, int c, int N) {
    __shared__ float sbuf[512];
    int b = blockIdx.x;
    int p = threadIdx.x;
    float sx = 0.f, sy = 0.f;
#pragma unroll
    for (int s = 0; s < MUSL; s++) {
        sx += g_muxp[s][b * c + p];
        sy += g_muyp[s][b * c + p];
    }
    float mx = sx / (float)N, my = sy / (float)N;
    g_mux[b * c + p] = mx;
    g_muy[b * c + p] = my;
    float tot = blockReduceSum(fabsf(mx - my), sbuf);
    if (p == 0) g_mud[lvl * BB + b] = tot / (float)c;
}

// ------------------------------ style: fused GEMM + cos-dist + min ----------
// 128x128 tile, BK=8, 256 threads, 8x8 microtile, fp32x2 packed FMA.
__global__ void __launch_bounds__(256) k_style(int c, int N, int lvl) {
    __shared__ float As[8][132];
    __shared__ float Bs[8][132];
    __shared__ float sRow[128], sCol[128];
    int b  = blockIdx.z;
    int i0 = blockIdx.y << 7;
    int j0 = blockIdx.x << 7;
    int t  = threadIdx.x;
    int tx = t & 15, ty = t >> 4;
    const float* X = g_X + (size_t)b * N * c;
    const float* Y = g_Y + (size_t)b * N * c;

    int lr = t >> 1;          // 0..127 (tile row for loads)
    int lk = (t & 1) << 2;    // 0 or 4

    ull acc[8][4];
#pragma unroll
    for (int ii = 0; ii < 8; ii++)
#pragma unroll
        for (int jh = 0; jh < 4; jh++) acc[ii][jh] = 0ULL;

    if (t < 128) { sRow[t] = FLT_MAX; sCol[t] = FLT_MAX; }

    int gi = i0 + lr, gj = j0 + lr;
    const float* xp = X + (size_t)gi * c + lk;
    const float* yp = Y + (size_t)gj * c + lk;
    float4 z4 = make_float4(0.f, 0.f, 0.f, 0.f);

    for (int k0 = 0; k0 < c; k0 += 8) {
        float4 xv = (gi < N) ? *reinterpret_cast<const float4*>(xp + k0) : z4;
        float4 yv = (gj < N) ? *reinterpret_cast<const float4*>(yp + k0) : z4;
        As[lk + 0][lr] = xv.x; As[lk + 1][lr] = xv.y; As[lk + 2][lr] = xv.z; As[lk + 3][lr] = xv.w;
        Bs[lk + 0][lr] = yv.x; Bs[lk + 1][lr] = yv.y; Bs[lk + 2][lr] = yv.z; Bs[lk + 3][lr] = yv.w;
        __syncthreads();
#pragma unroll
        for (int kk = 0; kk < 8; kk++) {
            float4 a0 = *reinterpret_cast<const float4*>(&As[kk][tx << 3]);
            float4 a1 = *reinterpret_cast<const float4*>(&As[kk][(tx << 3) + 4]);
            ulonglong2 b0 = *reinterpret_cast<const ulonglong2*>(&Bs[kk][ty << 3]);
            ulonglong2 b1 = *reinterpret_cast<const ulonglong2*>(&Bs[kk][(ty << 3) + 4]);
            ull bj[4] = {b0.x, b0.y, b1.x, b1.y};
            float aa[8] = {a0.x, a0.y, a0.z, a0.w, a1.x, a1.y, a1.z, a1.w};
#pragma unroll
            for (int ii = 0; ii < 8; ii++) {
                ull ad = dup2(aa[ii]);
#pragma unroll
                for (int jh = 0; jh < 4; jh++)
                    acc[ii][jh] = fma2(ad, bj[jh], acc[ii][jh]);
            }
        }
        __syncthreads();
    }

    float rn[8], cn[8];
#pragma unroll
    for (int ii = 0; ii < 8; ii++) {
        int i = i0 + (tx << 3) + ii;
        rn[ii] = (i < N) ? g_xn[b * N + i] : 0.f;
    }
#pragma unroll
    for (int jj = 0; jj < 8; jj++) {
        int j = j0 + (ty << 3) + jj;
        cn[jj] = (j < N) ? g_yn[b * N + j] : 0.f;
    }

    float rmin[8], cmin[8];
#pragma unroll
    for (int q = 0; q < 8; q++) { rmin[q] = FLT_MAX; cmin[q] = FLT_MAX; }

#pragma unroll
    for (int ii = 0; ii < 8; ii++) {
        int i = i0 + (tx << 3) + ii;
#pragma unroll
        for (int jh = 0; jh < 4; jh++) {
            float2 pv = unpk2(acc[ii][jh]);
            int jj0 = jh << 1;
            int j = j0 + (ty << 3) + jj0;
            float d0 = FLT_MAX, d1 = FLT_MAX;
            if (i < N && j < N)
                d0 = 1.f - pv.x / ((rn[ii] + EPSV) * (cn[jj0] + EPSV));
            if (i < N && (j + 1) < N)
                d1 = 1.f - pv.y / ((rn[ii] + EPSV) * (cn[jj0 + 1] + EPSV));
            rmin[ii] = fminf(rmin[ii], fminf(d0, d1));
            cmin[jj0]     = fminf(cmin[jj0], d0);
            cmin[jj0 + 1] = fminf(cmin[jj0 + 1], d1);
        }
    }
#pragma unroll
    for (int ii = 0; ii < 8; ii++) atomicMinF(&sRow[(tx << 3) + ii], rmin[ii]);
#pragma unroll
    for (int jj = 0; jj < 8; jj++) atomicMinF(&sCol[(ty << 3) + jj], cmin[jj]);
    __syncthreads();

    if (t < 128) {
        if (i0 + t < N) atomicMinF(&g_rowmin[(lvl * BB + b) * MAXN + i0 + t], sRow[t]);
        if (j0 + t < N) atomicMinF(&g_colmin[(lvl * BB + b) * MAXN + j0 + t], sCol[t]);
    }
}

// ------------------------------ cov: fused dual Gram + |diff| ---------------
// 64x64 tile of (p,q); tp<=tq (symmetry, weight 2 off-diag). fp32x2 packed FMA.
__global__ void __launch_bounds__(256) k_cov(int c, int N, int lvl) {
    __shared__ float Xp[16][68], Xq[16][68], Yp[16][68], Yq[16][68];
    __shared__ float sbuf[256];
    int b = blockIdx.y;
    int T = c >> 6;
    int pid = blockIdx.x;
    int tp = 0, rem = pid;
    while (rem >= T - tp) { rem -= (T - tp); tp++; }
    int tq = tp + rem;
    int p0 = tp << 6, q0 = tq << 6;

    const float* X = g_X + (size_t)b * N * c;
    const float* Y = g_Y + (size_t)b * N * c;
    int t = threadIdx.x;
    int tx = t & 15, ty = t >> 4;
    int lrow = t >> 4;
    int lcol = (t & 15) << 2;

    ull ax[4][2], ay[4][2];
#pragma unroll
    for (int xi = 0; xi < 4; xi++)
#pragma unroll
        for (int jh = 0; jh < 2; jh++) { ax[xi][jh] = 0ULL; ay[xi][jh] = 0ULL; }

    for (int k0 = 0; k0 < N; k0 += 16) {
        int i = k0 + lrow;
        float4 v0 = make_float4(0.f, 0.f, 0.f, 0.f), v1 = v0, v2 = v0, v3 = v0;
        if (i < N) {
            const float* xr = X + (size_t)i * c;
            const float* yr = Y + (size_t)i * c;
            v0 = *reinterpret_cast<const float4*>(xr + p0 + lcol);
            v1 = *reinterpret_cast<const float4*>(xr + q0 + lcol);
            v2 = *reinterpret_cast<const float4*>(yr + p0 + lcol);
            v3 = *reinterpret_cast<const float4*>(yr + q0 + lcol);
        }
        *reinterpret_cast<float4*>(&Xp[lrow][lcol]) = v0;
        *reinterpret_cast<float4*>(&Xq[lrow][lcol]) = v1;
        *reinterpret_cast<float4*>(&Yp[lrow][lcol]) = v2;
        *reinterpret_cast<float4*>(&Yq[lrow][lcol]) = v3;
        __syncthreads();
#pragma unroll
        for (int kk = 0; kk < 16; kk++) {
            float4 apv = *reinterpret_cast<const float4*>(&Xp[kk][tx << 2]);
            float4 bpv = *reinterpret_cast<const float4*>(&Yp[kk][tx << 2]);
            ulonglong2 aqv = *reinterpret_cast<const ulonglong2*>(&Xq[kk][ty << 2]);
            ulonglong2 bqv = *reinterpret_cast<const ulonglong2*>(&Yq[kk][ty << 2]);
            ull aq2[2] = {aqv.x, aqv.y};
            ull bq2[2] = {bqv.x, bqv.y};
            float ap[4] = {apv.x, apv.y, apv.z, apv.w};
            float bp[4] = {bpv.x, bpv.y, bpv.z, bpv.w};
#pragma unroll
            for (int xi = 0; xi < 4; xi++) {
                ull ad = dup2(ap[xi]);
                ull bd = dup2(bp[xi]);
#pragma unroll
                for (int jh = 0; jh < 2; jh++) {
                    ax[xi][jh] = fma2(ad, aq2[jh], ax[xi][jh]);
                    ay[xi][jh] = fma2(bd, bq2[jh], ay[xi][jh]);
                }
            }
        }
        __syncthreads();
    }

    float fn = (float)N;
    float inv = 1.f / (fn - 1.f);
    float mxp[4], mxq[4], myp[4], myq[4];
#pragma unroll
    for (int xi = 0; xi < 4; xi++) {
        int p = p0 + (tx << 2) + xi;
        mxp[xi] = g_mux[b * c + p];
        myp[xi] = g_muy[b * c + p];
    }
#pragma unroll
    for (int yj = 0; yj < 4; yj++) {
        int q = q0 + (ty << 2) + yj;
        mxq[yj] = g_mux[b * c + q];
        myq[yj] = g_muy[b * c + q];
    }
    float s = 0.f;
#pragma unroll
    for (int xi = 0; xi < 4; xi++)
#pragma unroll
        for (int jh = 0; jh < 2; jh++) {
            float2 gx2 = unpk2(ax[xi][jh]);
            float2 gy2 = unpk2(ay[xi][jh]);
            int j = jh << 1;
            float gx0 = gx2.x - fn * mxp[xi] * mxq[j];
            float gy0 = gy2.x - fn * myp[xi] * myq[j];
            float gx1 = gx2.y - fn * mxp[xi] * mxq[j + 1];
            float gy1 = gy2.y - fn * myp[xi] * myq[j + 1];
            s += fabsf((gx0 - gy0) * inv);
            s += fabsf((gx1 - gy1) * inv);
        }
    if (tp != tq) s *= 2.f;
    float tot = blockReduceSum(s, sbuf);
    if (t == 0) atomicAdd(&g_covsum[lvl * BB + b], tot);
}

// ------------------------------ style means ---------------------------------
__global__ void k_minmeans(int lvl, int N) {
    __shared__ float sbuf[256];
    int b = blockIdx.x;
    const float* rm = g_rowmin + (size_t)(lvl * BB + b) * MAXN;
    const float* cm = g_colmin + (size_t)(lvl * BB + b) * MAXN;
    float s1 = 0.f, s2 = 0.f;
    for (int i = threadIdx.x; i < N; i += 256) { s1 += rm[i]; s2 += cm[i]; }
    float t1 = blockReduceSum(s1, sbuf);
    float t2 = blockReduceSum(s2, sbuf);
    if (threadIdx.x == 0) {
        g_m1[lvl * BB + b] = t1 / (float)N;
        g_m2[lvl * BB + b] = t2 / (float)N;
    }
}

// ------------------------------ final ---------------------------------------
__global__ void k_final(float* out) {
    int t = threadIdx.x;
    float v = 0.f;
    if (t < 32) {
        int lvl = t >> 3;
        float cc = (float)(64 << lvl);
        float style = fmaxf(g_m1[t], g_m2[t]);
        v = style + g_mud[t] + g_covsum[t] / (cc * cc);
    }
#pragma unroll
    for (int o = 16; o > 0; o >>= 1) v += __shfl_down_sync(0xffffffff, v, o);
    if (t == 0) out[0] = v / (float)BB;
}

// ------------------------------ launch --------------------------------------
extern "C" void kernel_launch(void* const* d_in, const int* in_sizes, int n_in,
                              void* d_out, int out_size) {
    (void)out_size;
    const float* tf[4] = {0, 0, 0, 0};
    const float* gf[4] = {0, 0, 0, 0};
    const int* idxp[3] = {0, 0, 0};
    int tc[4] = {0, 0, 0, 0}, ic = 0;
    const long long lsz[4] = {33554432LL, 16777216LL, 8388608LL, 4194304LL};
    for (int i = 0; i < n_in; i++) {
        long long s = in_sizes[i];
        if (s == 8000LL) {
            if (ic < 3) idxp[ic++] = (const int*)d_in[i];
            continue;
        }
        for (int l = 0; l < 4; l++) {
            if (s == lsz[l]) {
                if (tc[l] == 0) tf[l] = (const float*)d_in[i];
                else            gf[l] = (const float*)d_in[i];
                tc[l]++;
                break;
            }
        }
    }

    const int Cs[4]  = {64, 128, 256, 512};
    const int Ns[4]  = {1000, 1000, 1000, 1024};
    const int HWs[4] = {65536, 16384, 4096, 1024};

    k_init<<<(4 * BB * MAXN + 255) / 256, 256>>>();

    for (int l = 0; l < 4; l++) {
        int c = Cs[l], N = Ns[l], hw = HWs[l];
        if (l < 3)
            k_gather<<<dim3(N, BB), 128>>>(tf[l], gf[l], idxp[l], c, hw, N);
        else
            k_transpose3<<<dim3(32, 16, BB), dim3(32, 8)>>>(tf[3], gf[3]);

        k_norms<<<BB * N, 128>>>(c);
        k_musum<<<dim3(c / 64, MUSL, BB), dim3(64, 4)>>>(c, N);
        k_mufin<<<BB, c>>>(l, c, N);

        int nt = (N + 127) / 128;
        k_style<<<dim3(nt, nt, BB), 256>>>(c, N, l);

        int T = c / 64, npairs = T * (T + 1) / 2;
        k_cov<<<dim3(npairs, BB), 256>>>(c, N, l);

        k_minmeans<<<BB, 256>>>(l, N);
    }
    k_final<<<1, 32>>>((float*)d_out);
}

// round 15
// speedup vs baseline: 2.0602x; 2.0602x over previous
#include <cuda_runtime.h>
#include <float.h>
#include <math.h>

#define BB 8
#define MAXN 1024
#define MAXC 512
#define EPSV 1e-10f
#define MUSL 8

// level offsets into packed point buffers (floats):
// l0: 8*1000*64 = 512000, l1: 8*1000*128 = 1024000,
// l2: 8*1000*256 = 2048000, l3: 8*1024*512 = 4194304  -> total 7778304
__device__ __forceinline__ size_t lvl_off(int l) {
    return (l == 0) ? 0ul : (l == 1) ? 512000ul : (l == 2) ? 1536000ul : 3584000ul;
}

// ------------------------- scratch (static device globals) -----------------
__device__ __align__(128) float g_X[7778304];
__device__ __align__(128) float g_Y[7778304];
__device__ float g_xn[4 * BB * MAXN];
__device__ float g_yn[4 * BB * MAXN];
__device__ float g_rowmin[4 * BB * MAXN];
__device__ float g_colmin[4 * BB * MAXN];
__device__ float g_muxp[MUSL][4 * BB * MAXC];
__device__ float g_muyp[MUSL][4 * BB * MAXC];
__device__ float g_mux[4 * BB * MAXC];
__device__ float g_muy[4 * BB * MAXC];
__device__ float g_mud[4 * BB];
__device__ float g_covsum[4 * BB];
__device__ float g_m1[4 * BB];
__device__ float g_m2[4 * BB];

// ------------------------------ helpers ------------------------------------
__device__ __forceinline__ void atomicMinF(float* addr, float val) {
    if (val >= 0.f) atomicMin((int*)addr, __float_as_int(val));
    else            atomicMax((unsigned int*)addr, __float_as_uint(val));
}

__device__ __forceinline__ float blockReduceSum(float v, float* sbuf) {
    int t = threadIdx.x + threadIdx.y * blockDim.x;
    int nt = blockDim.x * blockDim.y;
    __syncthreads();
    sbuf[t] = v;
    __syncthreads();
    for (int s = nt >> 1; s > 0; s >>= 1) {
        if (t < s) sbuf[t] += sbuf[t + s];
        __syncthreads();
    }
    return sbuf[0];
}

// ------------------------------ init ----------------------------------------
__global__ void k_init() {
    int i = blockIdx.x * blockDim.x + threadIdx.x;
    if (i < 4 * BB * MAXN) {
        g_rowmin[i] = FLT_MAX;
        g_colmin[i] = FLT_MAX;
    }
    if (i < 4 * BB) g_covsum[i] = 0.f;
}

// --------------------- gather + norms (levels 0-2, one launch) --------------
__global__ void k_gather_all(const float* __restrict__ tf0, const float* __restrict__ gf0, const int* __restrict__ ix0,
                             const float* __restrict__ tf1, const float* __restrict__ gf1, const int* __restrict__ ix1,
                             const float* __restrict__ tf2, const float* __restrict__ gf2, const int* __restrict__ ix2) {
    __shared__ float sbuf[128];
    int i = blockIdx.x;          // 0..999
    int z = blockIdx.y;          // lvl*8 + b
    int lvl = z >> 3, b = z & 7;
    const float* tf; const float* gf; const int* idx; int c, hw;
    if (lvl == 0)      { tf = tf0; gf = gf0; idx = ix0; c = 64;  hw = 65536; }
    else if (lvl == 1) { tf = tf1; gf = gf1; idx = ix1; c = 128; hw = 16384; }
    else               { tf = tf2; gf = gf2; idx = ix2; c = 256; hw = 4096; }
    const int N = 1000;
    int p = idx[b * N + i];
    const float* ts = tf + (size_t)b * c * hw + p;
    const float* gs = gf + (size_t)b * c * hw + p;
    size_t base = lvl_off(lvl) + ((size_t)b * N + i) * c;
    float sx = 0.f, sy = 0.f;
    for (int ch = threadIdx.x; ch < c; ch += 128) {
        float v = ts[(size_t)ch * hw];
        float w = gs[(size_t)ch * hw];
        g_X[base + ch] = v;
        g_Y[base + ch] = w;
        sx += v * v;
        sy += w * w;
    }
    float tx_ = blockReduceSum(sx, sbuf);
    float ty_ = blockReduceSum(sy, sbuf);
    if (threadIdx.x == 0) {
        g_xn[z * MAXN + i] = sqrtf(tx_);
        g_yn[z * MAXN + i] = sqrtf(ty_);
    }
}

// ------------------------------ level-3 transpose ---------------------------
__global__ void k_transpose3(const float* __restrict__ tf, const float* __restrict__ gf) {
    __shared__ float st[32][33];
    __shared__ float sg[32][33];
    int b  = blockIdx.z;
    int i0 = blockIdx.x << 5;
    int c0 = blockIdx.y << 5;
    int tx = threadIdx.x;
    int ty = threadIdx.y;
    const float* tb = tf + ((size_t)(b * 512 + c0)) * 1024 + i0;
    const float* gb = gf + ((size_t)(b * 512 + c0)) * 1024 + i0;
    for (int r = ty; r < 32; r += 8) {
        st[r][tx] = tb[(size_t)r * 1024 + tx];
        sg[r][tx] = gb[(size_t)r * 1024 + tx];
    }
    __syncthreads();
    size_t base = 3584000ul + (size_t)b * 524288ul;
    for (int r = ty; r < 32; r += 8) {
        g_X[base + (size_t)(i0 + r) * 512 + c0 + tx] = st[tx][r];
        g_Y[base + (size_t)(i0 + r) * 512 + c0 + tx] = sg[tx][r];
    }
}

// ------------------------ norms for level 3 (from original layout) ----------
__global__ void k_norms3(const float* __restrict__ tf, const float* __restrict__ gf) {
    __shared__ float sx[8][33], sy[8][33];
    int b  = blockIdx.y;
    int i0 = blockIdx.x << 5;
    int tx = threadIdx.x, ty = threadIdx.y;
    const float* tb = tf + (size_t)b * 512 * 1024 + i0 + tx;
    const float* gb = gf + (size_t)b * 512 * 1024 + i0 + tx;
    float ax = 0.f, ay = 0.f;
    for (int ch = ty; ch < 512; ch += 8) {
        float v = tb[(size_t)ch * 1024]; ax += v * v;
        float w = gb[(size_t)ch * 1024]; ay += w * w;
    }
    sx[ty][tx] = ax;
    sy[ty][tx] = ay;
    __syncthreads();
    if (ty == 0) {
        float a = 0.f, c2 = 0.f;
#pragma unroll
        for (int k = 0; k < 8; k++) { a += sx[k][tx]; c2 += sy[k][tx]; }
        int z = 3 * BB + b;
        g_xn[z * MAXN + i0 + tx] = sqrtf(a);
        g_yn[z * MAXN + i0 + tx] = sqrtf(c2);
    }
}

// ------------------------------ mu partial sums (all levels) ----------------
__global__ void k_musum_all() {
    __shared__ float shx[8][64], shy[8][64];
    int z   = blockIdx.z;        // lvl*8 + b
    int lvl = z >> 3, b = z & 7;
    int c = 64 << lvl;
    int N = (lvl == 3) ? 1024 : 1000;
    if ((blockIdx.x << 6) >= c) return;
    int sl = blockIdx.y;
    int ch = (blockIdx.x << 6) + threadIdx.x;
    int len = (N + MUSL - 1) / MUSL;
    int r0 = sl * len;
    int r1 = min(N, r0 + len);
    const float* x = g_X + lvl_off(lvl) + (size_t)b * N * c + ch;
    const float* y = g_Y + lvl_off(lvl) + (size_t)b * N * c + ch;
    float sx = 0.f, sy = 0.f;
    for (int i = r0 + threadIdx.y; i < r1; i += 8) {
        sx += x[(size_t)i * c];
        sy += y[(size_t)i * c];
    }
    shx[threadIdx.y][threadIdx.x] = sx;
    shy[threadIdx.y][threadIdx.x] = sy;
    __syncthreads();
    if (threadIdx.y == 0) {
        float ax = 0.f, ay = 0.f;
#pragma unroll
        for (int k = 0; k < 8; k++) { ax += shx[k][threadIdx.x]; ay += shy[k][threadIdx.x]; }
        g_muxp[sl][z * MAXC + ch] = ax;
        g_muyp[sl][z * MAXC + ch] = ay;
    }
}

// ------------------------------ mu finalize + mu_d (all levels) -------------
__global__ void k_mufin_all() {
    __shared__ float sbuf[512];
    int z   = blockIdx.x;        // lvl*8 + b
    int lvl = z >> 3;
    int c = 64 << lvl;
    int N = (lvl == 3) ? 1024 : 1000;
    int p = threadIdx.x;
    float v = 0.f;
    if (p < c) {
        float sx = 0.f, sy = 0.f;
#pragma unroll
        for (int s = 0; s < MUSL; s++) {
            sx += g_muxp[s][z * MAXC + p];
            sy += g_muyp[s][z * MAXC + p];
        }
        float mx = sx / (float)N, my = sy / (float)N;
        g_mux[z * MAXC + p] = mx;
        g_muy[z * MAXC + p] = my;
        v = fabsf(mx - my);
    }
    float tot = blockReduceSum(v, sbuf);
    if (p == 0) g_mud[z] = tot / (float)c;
}

// ======================= fused main: style GEMM + cov GEMM ==================
// Block schedule (expensive first): cov-l3(288), style-l3(512), cov-l2(80),
// style-l2(512), cov-l1(24), style-l1(512), cov-l0(8), style-l0(512) = 2448.
__global__ void __launch_bounds__(256) k_main() {
    __shared__ float SH[4608];
    int bid = blockIdx.x;
    int t = threadIdx.x;
    int tx = t & 15, ty = t >> 4;

    bool isStyle;
    int lvl, b, rem;   // style: rem = tile index 0..63 ; cov: rem = pair id
    if (bid < 288)        { isStyle = false; lvl = 3; b = bid & 7;            rem = bid >> 3; }
    else if (bid < 800)   { isStyle = true;  lvl = 3; int s = bid - 288;  b = s >> 6; rem = s & 63; }
    else if (bid < 880)   { isStyle = false; lvl = 2; int s = bid - 800;  b = s & 7;  rem = s >> 3; }
    else if (bid < 1392)  { isStyle = true;  lvl = 2; int s = bid - 880;  b = s >> 6; rem = s & 63; }
    else if (bid < 1416)  { isStyle = false; lvl = 1; int s = bid - 1392; b = s & 7;  rem = s >> 3; }
    else if (bid < 1928)  { isStyle = true;  lvl = 1; int s = bid - 1416; b = s >> 6; rem = s & 63; }
    else if (bid < 1936)  { isStyle = false; lvl = 0; int s = bid - 1928; b = s & 7;  rem = 0; }
    else                  { isStyle = true;  lvl = 0; int s = bid - 1936; b = s >> 6; rem = s & 63; }

    int c = 64 << lvl;
    int N = (lvl == 3) ? 1024 : 1000;
    int zi = lvl * BB + b;
    const float* X = g_X + lvl_off(lvl) + (size_t)b * N * c;
    const float* Y = g_Y + lvl_off(lvl) + (size_t)b * N * c;
    float4 z4 = make_float4(0.f, 0.f, 0.f, 0.f);

    if (isStyle) {
        // ---------- style: 128x128 tile, BK=8, double-buffered, 8x8 micro ----
        float* As   = SH;               // [2][8][132] = 2112
        float* Bs   = SH + 2112;        // 2112
        float* sRow = SH + 4224;        // 128
        float* sCol = SH + 4352;        // 128
        int i0 = (rem >> 3) << 7;
        int j0 = (rem & 7) << 7;
        int lr = t >> 1;
        int lk = (t & 1) << 2;
        int gi = i0 + lr, gj = j0 + lr;
        const float* xp = X + (size_t)gi * c + lk;
        const float* yp = Y + (size_t)gj * c + lk;

        float acc[8][8];
#pragma unroll
        for (int ii = 0; ii < 8; ii++)
#pragma unroll
            for (int jj = 0; jj < 8; jj++) acc[ii][jj] = 0.f;

        if (t < 128) { sRow[t] = FLT_MAX; sCol[t] = FLT_MAX; }

        // preload tile 0 into buffer 0
        {
            float4 cA = (gi < N) ? *reinterpret_cast<const float4*>(xp) : z4;
            float4 cB = (gj < N) ? *reinterpret_cast<const float4*>(yp) : z4;
            As[(lk + 0) * 132 + lr] = cA.x; As[(lk + 1) * 132 + lr] = cA.y;
            As[(lk + 2) * 132 + lr] = cA.z; As[(lk + 3) * 132 + lr] = cA.w;
            Bs[(lk + 0) * 132 + lr] = cB.x; Bs[(lk + 1) * 132 + lr] = cB.y;
            Bs[(lk + 2) * 132 + lr] = cB.z; Bs[(lk + 3) * 132 + lr] = cB.w;
        }
        __syncthreads();

        for (int k0 = 0; k0 < c; k0 += 8) {
            int buf = (k0 >> 3) & 1;
            int kn = k0 + 8;
            float4 nA = z4, nB = z4;
            if (kn < c) {
                nA = (gi < N) ? *reinterpret_cast<const float4*>(xp + kn) : z4;
                nB = (gj < N) ? *reinterpret_cast<const float4*>(yp + kn) : z4;
            }
            const float* A = As + buf * 1056;
            const float* B = Bs + buf * 1056;
#pragma unroll
            for (int kk = 0; kk < 8; kk++) {
                float4 a0 = *reinterpret_cast<const float4*>(&A[kk * 132 + (tx << 3)]);
                float4 a1 = *reinterpret_cast<const float4*>(&A[kk * 132 + (tx << 3) + 4]);
                float4 b0 = *reinterpret_cast<const float4*>(&B[kk * 132 + (ty << 3)]);
                float4 b1 = *reinterpret_cast<const float4*>(&B[kk * 132 + (ty << 3) + 4]);
                float aa[8] = {a0.x, a0.y, a0.z, a0.w, a1.x, a1.y, a1.z, a1.w};
                float bb[8] = {b0.x, b0.y, b0.z, b0.w, b1.x, b1.y, b1.z, b1.w};
#pragma unroll
                for (int ii = 0; ii < 8; ii++)
#pragma unroll
                    for (int jj = 0; jj < 8; jj++)
                        acc[ii][jj] += aa[ii] * bb[jj];
            }
            if (kn < c) {
                float* An = As + (buf ^ 1) * 1056;
                float* Bn = Bs + (buf ^ 1) * 1056;
                An[(lk + 0) * 132 + lr] = nA.x; An[(lk + 1) * 132 + lr] = nA.y;
                An[(lk + 2) * 132 + lr] = nA.z; An[(lk + 3) * 132 + lr] = nA.w;
                Bn[(lk + 0) * 132 + lr] = nB.x; Bn[(lk + 1) * 132 + lr] = nB.y;
                Bn[(lk + 2) * 132 + lr] = nB.z; Bn[(lk + 3) * 132 + lr] = nB.w;
            }
            __syncthreads();
        }

        float rn[8], cn[8];
#pragma unroll
        for (int ii = 0; ii < 8; ii++) {
            int i = i0 + (tx << 3) + ii;
            rn[ii] = (i < N) ? g_xn[zi * MAXN + i] : 0.f;
        }
#pragma unroll
        for (int jj = 0; jj < 8; jj++) {
            int j = j0 + (ty << 3) + jj;
            cn[jj] = (j < N) ? g_yn[zi * MAXN + j] : 0.f;
        }

        float rmin[8], cmin[8];
#pragma unroll
        for (int q = 0; q < 8; q++) { rmin[q] = FLT_MAX; cmin[q] = FLT_MAX; }
#pragma unroll
        for (int ii = 0; ii < 8; ii++) {
            int i = i0 + (tx << 3) + ii;
#pragma unroll
            for (int jj = 0; jj < 8; jj++) {
                int j = j0 + (ty << 3) + jj;
                float d = FLT_MAX;
                if (i < N && j < N)
                    d = 1.f - acc[ii][jj] / ((rn[ii] + EPSV) * (cn[jj] + EPSV));
                rmin[ii] = fminf(rmin[ii], d);
                cmin[jj] = fminf(cmin[jj], d);
            }
        }
#pragma unroll
        for (int ii = 0; ii < 8; ii++) atomicMinF(&sRow[(tx << 3) + ii], rmin[ii]);
#pragma unroll
        for (int jj = 0; jj < 8; jj++) atomicMinF(&sCol[(ty << 3) + jj], cmin[jj]);
        __syncthreads();

        if (t < 128) {
            if (i0 + t < N) atomicMinF(&g_rowmin[zi * MAXN + i0 + t], sRow[t]);
            if (j0 + t < N) atomicMinF(&g_colmin[zi * MAXN + j0 + t], sCol[t]);
        }
    } else {
        // ---------- cov: 64x64 tile of (p,q), tp<=tq, BK=16, scalar ----------
        float* Xp   = SH;            // 16*68 = 1088
        float* Xq   = SH + 1088;
        float* Yp   = SH + 2176;
        float* Yq   = SH + 3264;
        float* sbuf = SH + 4352;     // 256

        int T = c >> 6;
        int tp = 0, r2 = rem;
        while (r2 >= T - tp) { r2 -= (T - tp); tp++; }
        int tq = tp + r2;
        int p0 = tp << 6, q0 = tq << 6;

        int lrow = t >> 4;
        int lcol = (t & 15) << 2;

        float ax[4][4], ay[4][4];
#pragma unroll
        for (int xi = 0; xi < 4; xi++)
#pragma unroll
            for (int yj = 0; yj < 4; yj++) { ax[xi][yj] = 0.f; ay[xi][yj] = 0.f; }

        for (int k0 = 0; k0 < N; k0 += 16) {
            int i = k0 + lrow;
            float4 v0 = z4, v1 = z4, v2 = z4, v3 = z4;
            if (i < N) {
                const float* xr = X + (size_t)i * c;
                const float* yr = Y + (size_t)i * c;
                v0 = *reinterpret_cast<const float4*>(xr + p0 + lcol);
                v1 = *reinterpret_cast<const float4*>(xr + q0 + lcol);
                v2 = *reinterpret_cast<const float4*>(yr + p0 + lcol);
                v3 = *reinterpret_cast<const float4*>(yr + q0 + lcol);
            }
            *reinterpret_cast<float4*>(&Xp[lrow * 68 + lcol]) = v0;
            *reinterpret_cast<float4*>(&Xq[lrow * 68 + lcol]) = v1;
            *reinterpret_cast<float4*>(&Yp[lrow * 68 + lcol]) = v2;
            *reinterpret_cast<float4*>(&Yq[lrow * 68 + lcol]) = v3;
            __syncthreads();
#pragma unroll
            for (int kk = 0; kk < 16; kk++) {
                float4 apv = *reinterpret_cast<const float4*>(&Xp[kk * 68 + (tx << 2)]);
                float4 aqv = *reinterpret_cast<const float4*>(&Xq[kk * 68 + (ty << 2)]);
                float4 bpv = *reinterpret_cast<const float4*>(&Yp[kk * 68 + (tx << 2)]);
                float4 bqv = *reinterpret_cast<const float4*>(&Yq[kk * 68 + (ty << 2)]);
                float ap[4] = {apv.x, apv.y, apv.z, apv.w};
                float aq[4] = {aqv.x, aqv.y, aqv.z, aqv.w};
                float bp[4] = {bpv.x, bpv.y, bpv.z, bpv.w};
                float bq[4] = {bqv.x, bqv.y, bqv.z, bqv.w};
#pragma unroll
                for (int xi = 0; xi < 4; xi++)
#pragma unroll
                    for (int yj = 0; yj < 4; yj++) {
                        ax[xi][yj] += ap[xi] * aq[yj];
                        ay[xi][yj] += bp[xi] * bq[yj];
                    }
            }
            __syncthreads();
        }

        float fn = (float)N;
        float inv = 1.f / (fn - 1.f);
        float mxp[4], mxq[4], myp[4], myq[4];
#pragma unroll
        for (int xi = 0; xi < 4; xi++) {
            int p = p0 + (tx << 2) + xi;
            mxp[xi] = g_mux[zi * MAXC + p];
            myp[xi] = g_muy[zi * MAXC + p];
        }
#pragma unroll
        for (int yj = 0; yj < 4; yj++) {
            int q = q0 + (ty << 2) + yj;
            mxq[yj] = g_mux[zi * MAXC + q];
            myq[yj] = g_muy[zi * MAXC + q];
        }
        float s = 0.f;
#pragma unroll
        for (int xi = 0; xi < 4; xi++)
#pragma unroll
            for (int yj = 0; yj < 4; yj++) {
                float gx = ax[xi][yj] - fn * mxp[xi] * mxq[yj];
                float gy = ay[xi][yj] - fn * myp[xi] * myq[yj];
                s += fabsf((gx - gy) * inv);
            }
        if (tp != tq) s *= 2.f;
        float tot = blockReduceSum(s, sbuf);
        if (t == 0) atomicAdd(&g_covsum[zi], tot);
    }
}

// ------------------------------ style means (all levels) --------------------
__global__ void k_minmeans_all() {
    __shared__ float sbuf[256];
    int z = blockIdx.x;          // lvl*8 + b
    int lvl = z >> 3;
    int N = (lvl == 3) ? 1024 : 1000;
    const float* rm = g_rowmin + (size_t)z * MAXN;
    const float* cm = g_colmin + (size_t)z * MAXN;
    float s1 = 0.f, s2 = 0.f;
    for (int i = threadIdx.x; i < N; i += 256) { s1 += rm[i]; s2 += cm[i]; }
    float t1 = blockReduceSum(s1, sbuf);
    float t2 = blockReduceSum(s2, sbuf);
    if (threadIdx.x == 0) {
        g_m1[z] = t1 / (float)N;
        g_m2[z] = t2 / (float)N;
    }
}

// ------------------------------ final ---------------------------------------
__global__ void k_final(float* out) {
    int t = threadIdx.x;
    float v = 0.f;
    if (t < 32) {
        int lvl = t >> 3;
        float cc = (float)(64 << lvl);
        float style = fmaxf(g_m1[t], g_m2[t]);
        v = style + g_mud[t] + g_covsum[t] / (cc * cc);
    }
#pragma unroll
    for (int o = 16; o > 0; o >>= 1) v += __shfl_down_sync(0xffffffff, v, o);
    if (t == 0) out[0] = v / (float)BB;
}

// ------------------------------ launch --------------------------------------
extern "C" void kernel_launch(void* const* d_in, const int* in_sizes, int n_in,
                              void* d_out, int out_size) {
    (void)out_size;
    const float* tf[4] = {0, 0, 0, 0};
    const float* gf[4] = {0, 0, 0, 0};
    const int* idxp[3] = {0, 0, 0};
    int tc[4] = {0, 0, 0, 0}, ic = 0;
    const long long lsz[4] = {33554432LL, 16777216LL, 8388608LL, 4194304LL};
    for (int i = 0; i < n_in; i++) {
        long long s = in_sizes[i];
        if (s == 8000LL) {
            if (ic < 3) idxp[ic++] = (const int*)d_in[i];
            continue;
        }
        for (int l = 0; l < 4; l++) {
            if (s == lsz[l]) {
                if (tc[l] == 0) tf[l] = (const float*)d_in[i];
                else            gf[l] = (const float*)d_in[i];
                tc[l]++;
                break;
            }
        }
    }

    k_init<<<(4 * BB * MAXN + 255) / 256, 256>>>();

    k_gather_all<<<dim3(1000, 24), 128>>>(tf[0], gf[0], idxp[0],
                                          tf[1], gf[1], idxp[1],
                                          tf[2], gf[2], idxp[2]);
    k_transpose3<<<dim3(32, 16, BB), dim3(32, 8)>>>(tf[3], gf[3]);
    k_norms3<<<dim3(32, BB), dim3(32, 8)>>>(tf[3], gf[3]);

    k_musum_all<<<dim3(8, MUSL, 32), dim3(64, 8)>>>();
    k_mufin_all<<<32, 512>>>();

    k_main<<<2448, 256>>>();

    k_minmeans_all<<<32, 256>>>();
    k_final<<<1, 32>>>((float*)d_out);
}